// round 13
// baseline (speedup 1.0000x reference)
#include <cuda_runtime.h>
#include <cuda_bf16.h>

// Problem constants (fixed by reference: Z=2, N=256, A=14, AA=21, voxel 16^3, RES=1)
namespace {
constexpr int NA   = 14;
constexpr int ZN   = 2 * 256;               // 512 residues
constexpr int VOX  = 16;
constexpr int VOXELS = VOX * VOX * VOX;     // 4096
constexpr size_t BB_BASE  = 0;                                   // (ZN,4,3)
constexpr size_t DIV_BASE = (size_t)ZN * 12;                     // (ZN,1,16,16,16)
constexpr size_t FR_BASE  = DIV_BASE + (size_t)ZN * VOXELS;      // (ZN,3,3)
}

// 4 CTAs per residue: (half_y, half_x). 128 threads = (y in 8 planes) x (v in 16).
// Each thread covers 9 x-values (8 owned + 1 halo) so the central-difference
// stencil stays register-resident: accumulators 27 regs instead of 48.
// __launch_bounds__(128, 9): 55-reg cap -> 9 CTAs/SM -> 36 warps/SM.
__global__ __launch_bounds__(128, 9)
void pp_kernel(const float* __restrict__ C,
               const int*   __restrict__ Lw,     // int32 view of L (int32 OR int64 storage)
               const float* __restrict__ amask,
               const float* __restrict__ amber,
               float* __restrict__ out)
{
    const int rn     = blockIdx.x >> 2;
    const int half_y = (blockIdx.x >> 1) & 1;
    const int half_x = blockIdx.x & 1;
    const int t      = threadIdx.x;     // y_lo = t>>4, v = t&15

    __shared__ float4 s_atom[NA];       // x,y,z,charge

    const float* Cr = C + (size_t)rn * NA * 3;

    // ---- atom + charge load (threads 0..13) ----
    if (t < NA) {
        // Detect int64-vs-int32 storage of L (values in [-1,20]): for int64 (LE)
        // every odd 32-bit word is 0 or -1; misdetect prob for int32 ~21^-16.
        int bad = 0;
        #pragma unroll
        for (int k = 0; k < 16; ++k) {
            int hv = __ldg(Lw + 2 * k + 1);
            bad |= (hv != 0) & (hv != -1);
        }
        int lv = bad ? __ldg(Lw + rn) : __ldg(Lw + 2 * rn);
        int lc = (lv == -1) ? 20 : lv;       // X_LBL = 20
        float q = __ldg(amber + lc * NA + t) * __ldg(amask + (size_t)rn * NA + t);
        s_atom[t] = make_float4(__ldg(Cr + 3 * t),
                                __ldg(Cr + 3 * t + 1),
                                __ldg(Cr + 3 * t + 2), q);
    }

    // ---- frame build (redundant per thread; broadcast loads; block-uniform) ----
    float n0 = __ldg(Cr + 0), n1 = __ldg(Cr + 1), n2 = __ldg(Cr + 2);
    float a0 = __ldg(Cr + 3), a1 = __ldg(Cr + 4), a2 = __ldg(Cr + 5);
    float c0 = __ldg(Cr + 6), c1 = __ldg(Cr + 7), c2 = __ldg(Cr + 8);

    float b1x = a0 - n0, b1y = a1 - n1, b1z = a2 - n2;
    float b2x = c0 - a0, b2y = c1 - a1, b2z = c2 - a2;
    float b3x = b1y * b2z - b1z * b2y;
    float b3y = b1z * b2x - b1x * b2z;
    float b3z = b1x * b2y - b1y * b2x;
    float cb0 = a0 - 0.58273431f * b2x + 0.56802827f * b1x - 0.54067466f * b3x;
    float cb1 = a1 - 0.58273431f * b2y + 0.56802827f * b1y - 0.54067466f * b3y;
    float cb2 = a2 - 0.58273431f * b2z + 0.56802827f * b1z - 0.54067466f * b3z;

    float yx = cb0 - a0, yy = cb1 - a1, yz = cb2 - a2;
    float yn = sqrtf(yx * yx + yy * yy + yz * yz);
    float yi = 1.0f / fmaxf(yn, 1e-6f);
    float yux = yx * yi, yuy = yy * yi, yuz = yz * yi;

    // scalar projection subtracted from every component (replicates reference)
    float xrx = c0 - n0, xry = c1 - n1, xrz = c2 - n2;
    float xp = xrx * yux + xry * yuy + xrz * yuz;
    float xx = xrx - xp, xy = xry - xp, xz = xrz - xp;
    float xn = sqrtf(xx * xx + xy * xy + xz * xz);
    float xi = 1.0f / fmaxf(xn, 1e-6f);
    float xux = xx * xi, xuy = xy * xi, xuz = xz * xi;

    float zux = xuy * yuz - xuz * yuy;
    float zuy = xuz * yux - xux * yuz;
    float zuz = xux * yuy - xuy * yux;

    if (half_y == 0 && half_x == 0 && t == 0) {
        float* bb = out + BB_BASE + (size_t)rn * 12;
        bb[0] = n0;  bb[1] = n1;  bb[2] = n2;
        bb[3] = a0;  bb[4] = a1;  bb[5] = a2;
        bb[6] = c0;  bb[7] = c1;  bb[8] = c2;
        bb[9] = cb0; bb[10] = cb1; bb[11] = cb2;
        float* fr = out + FR_BASE + (size_t)rn * 9;
        fr[0] = xux; fr[1] = xuy; fr[2] = xuz;
        fr[3] = yux; fr[4] = yuy; fr[5] = yuz;
        fr[6] = zux; fr[7] = zuy; fr[8] = zuz;
    }

    __syncthreads();

    // ---- per-thread column base for (y,v), shifted to this half's first x ----
    const int   yidx = half_y * 8 + (t >> 4);
    const float gy = (float)yidx - 4.0f;        // VY/4
    const float gz = (float)(t & 15) - 8.0f;    // VZ/2
    // gx for local k: gx = gx0 + k, k = 0..8
    //   half_x=0: x = 0..8  -> gx0 = -8
    //   half_x=1: x = 7..15 -> gx0 = -1
    const float gx0 = half_x ? -1.0f : -8.0f;
    float px = cb0 + gy * yux + gz * zux + gx0 * xux;
    float py = cb1 + gy * yuy + gz * zuy + gx0 * xuy;
    float pz = cb2 + gy * yuz + gz * zuz + gx0 * xuz;

    float Fx[9], Fy[9], Fz[9];
    #pragma unroll
    for (int k = 0; k < 9; ++k) { Fx[k] = 0.f; Fy[k] = 0.f; Fz[k] = 0.f; }

    // hot loop: 14 atoms x 9 x-values, fully unrolled. k is a compile-time
    // integer -> d = k*xu + q uses the FFMA-imm form (rt=1 on that op).
    // Weight: w = w0 * ry * sat(ry^2), ry = rsqrt(r2 + 1e-30) (same as R5/R9).
    #pragma unroll
    for (int a = 0; a < NA; ++a) {
        float4 at = s_atom[a];
        float qx = px - at.x, qy = py - at.y, qz = pz - at.z;
        float w0 = at.w;
        #pragma unroll
        for (int k = 0; k < 9; ++k) {
            float fk = (float)k;
            float dx = fmaf(fk, xux, qx);
            float dy = fmaf(fk, xuy, qy);
            float dz = fmaf(fk, xuz, qz);
            float r2 = fmaf(dx, dx, fmaf(dy, dy, fmaf(dz, dz, 1e-30f)));
            float ry = rsqrtf(r2);
            float w  = w0 * (ry * __saturatef(ry * ry));
            Fx[k] = fmaf(w, dx, Fx[k]);
            Fy[k] = fmaf(w, dy, Fy[k]);
            Fz[k] = fmaf(w, dz, Fz[k]);
        }
    }

    // ---- normalize field vectors (per voxel, halo included) ----
    #pragma unroll
    for (int k = 0; k < 9; ++k) {
        float s = fmaf(Fx[k], Fx[k], fmaf(Fy[k], Fy[k], Fz[k] * Fz[k]));
        float sc = (s > 0.0f) ? rsqrtf(s) : 1.0f;
        Fx[k] *= sc; Fy[k] *= sc; Fz[k] *= sc;
    }

    // ---- divergence along VX (axis 2); x: flip_last=False, y/z: True ----
    // out index = rn*4096 + x*256 + (yidx*16 + v);  yidx*16+v = half_y*128 + t
    float* dv = out + DIV_BASE + (size_t)rn * VOXELS + (half_y * 128 + t);
    if (half_x == 0) {
        // local k == global x (0..8); write x = 0..7
        dv[0] = (Fx[1] - Fx[0]) + (Fy[1] - Fy[0]) + (Fz[1] - Fz[0]);
        #pragma unroll
        for (int i = 1; i <= 7; ++i) {
            float d = 0.5f * (Fx[i + 1] - Fx[i - 1])
                    + 0.5f * (Fy[i + 1] - Fy[i - 1])
                    + 0.5f * (Fz[i + 1] - Fz[i - 1]);
            dv[i * 256] = d;
        }
    } else {
        // local k maps to global x = 7 + k; write x = 8..15
        #pragma unroll
        for (int j = 0; j <= 6; ++j) {     // global x = 8+j, neighbors k=j, k=j+2
            float d = 0.5f * (Fx[j + 2] - Fx[j])
                    + 0.5f * (Fy[j + 2] - Fy[j])
                    + 0.5f * (Fz[j + 2] - Fz[j]);
            dv[(8 + j) * 256] = d;
        }
        // global x = 15: local 8 and 7
        dv[15 * 256] = (Fx[8] - Fx[7]) + (Fy[7] - Fy[8]) + (Fz[7] - Fz[8]);
    }
}

extern "C" void kernel_launch(void* const* d_in, const int* in_sizes, int n_in,
                              void* d_out, int out_size)
{
    const float* C     = (const float*)d_in[0];
    const int*   Lw    = (const int*)  d_in[1];   // int32 view; width auto-detected
    const float* amask = (const float*)d_in[2];
    // d_in[3] = valid_mask: unused by the reference
    const float* amber = (const float*)d_in[4];

    pp_kernel<<<ZN * 4, 128>>>(C, Lw, amask, amber, (float*)d_out);
}

// round 14
// speedup vs baseline: 1.1018x; 1.1018x over previous
#include <cuda_runtime.h>
#include <cuda_bf16.h>

// Problem constants (fixed by reference: Z=2, N=256, A=14, AA=21, voxel 16^3, RES=1)
namespace {
constexpr int NA   = 14;
constexpr int ZN   = 2 * 256;               // 512 residues
constexpr int VOX  = 16;
constexpr int VOXELS = VOX * VOX * VOX;     // 4096
constexpr size_t BB_BASE  = 0;                                   // (ZN,4,3)
constexpr size_t DIV_BASE = (size_t)ZN * 12;                     // (ZN,1,16,16,16)
constexpr size_t FR_BASE  = DIV_BASE + (size_t)ZN * VOXELS;      // (ZN,3,3)
}

// 4 CTAs per residue; CTA = 64 (y,v) columns x 2 x-halves = 128 threads.
// Each thread integrates 8 x-values (24 accumulator regs, NO halo -- the
// stencil boundary F[7]/F[8] is exchanged through SMEM inside the CTA).
// __launch_bounds__(128, 9): 56-reg cap -> 9 CTAs/SM -> 36 warps/SM.
// Grid 2048: ~13.8 CTAs/SM over ~1.5 occupancy-rounds; per R12 evidence the
// higher occupancy raises issue from ~60% to ~82%.
__global__ __launch_bounds__(128, 9)
void pp_kernel(const float* __restrict__ C,
               const int*   __restrict__ Lw,     // int32 view of L (int32 OR int64 storage)
               const float* __restrict__ amask,
               const float* __restrict__ amber,
               float* __restrict__ out)
{
    const int rn  = blockIdx.x >> 2;    // residue
    const int qy  = blockIdx.x & 3;     // which 4 y-planes
    const int t   = threadIdx.x;
    const int xh  = t >> 6;             // x-half: 0 -> x 0..7, 1 -> x 8..15
    const int col = t & 63;             // column in this quarter: y_lo = col>>4, v = col&15

    __shared__ float4 s_atom[NA];           // x,y,z,charge
    __shared__ float  sEdge[2][3][64];      // [xh][comp][col]: normalized F at x=7 / x=8

    const float* Cr = C + (size_t)rn * NA * 3;

    // ---- atom + charge load (threads 0..13) ----
    if (t < NA) {
        // Detect int64-vs-int32 storage of L (values in [-1,20]): for int64 (LE)
        // every odd 32-bit word is 0 or -1; misdetect prob for int32 ~21^-16.
        int bad = 0;
        #pragma unroll
        for (int k = 0; k < 16; ++k) {
            int hv = __ldg(Lw + 2 * k + 1);
            bad |= (hv != 0) & (hv != -1);
        }
        int lv = bad ? __ldg(Lw + rn) : __ldg(Lw + 2 * rn);
        int lc = (lv == -1) ? 20 : lv;       // X_LBL = 20
        float q = __ldg(amber + lc * NA + t) * __ldg(amask + (size_t)rn * NA + t);
        s_atom[t] = make_float4(__ldg(Cr + 3 * t),
                                __ldg(Cr + 3 * t + 1),
                                __ldg(Cr + 3 * t + 2), q);
    }

    // ---- frame build (redundant per thread; broadcast loads; block-uniform) ----
    float n0 = __ldg(Cr + 0), n1 = __ldg(Cr + 1), n2 = __ldg(Cr + 2);
    float a0 = __ldg(Cr + 3), a1 = __ldg(Cr + 4), a2 = __ldg(Cr + 5);
    float c0 = __ldg(Cr + 6), c1 = __ldg(Cr + 7), c2 = __ldg(Cr + 8);

    float b1x = a0 - n0, b1y = a1 - n1, b1z = a2 - n2;
    float b2x = c0 - a0, b2y = c1 - a1, b2z = c2 - a2;
    float b3x = b1y * b2z - b1z * b2y;
    float b3y = b1z * b2x - b1x * b2z;
    float b3z = b1x * b2y - b1y * b2x;
    float cb0 = a0 - 0.58273431f * b2x + 0.56802827f * b1x - 0.54067466f * b3x;
    float cb1 = a1 - 0.58273431f * b2y + 0.56802827f * b1y - 0.54067466f * b3y;
    float cb2 = a2 - 0.58273431f * b2z + 0.56802827f * b1z - 0.54067466f * b3z;

    float yx = cb0 - a0, yy = cb1 - a1, yz = cb2 - a2;
    float yn = sqrtf(yx * yx + yy * yy + yz * yz);
    float yi = 1.0f / fmaxf(yn, 1e-6f);
    float yux = yx * yi, yuy = yy * yi, yuz = yz * yi;

    // scalar projection subtracted from every component (replicates reference)
    float xrx = c0 - n0, xry = c1 - n1, xrz = c2 - n2;
    float xp = xrx * yux + xry * yuy + xrz * yuz;
    float xx = xrx - xp, xy = xry - xp, xz = xrz - xp;
    float xn = sqrtf(xx * xx + xy * xy + xz * xz);
    float xi = 1.0f / fmaxf(xn, 1e-6f);
    float xux = xx * xi, xuy = xy * xi, xuz = xz * xi;

    float zux = xuy * yuz - xuz * yuy;
    float zuy = xuz * yux - xux * yuz;
    float zuz = xux * yuy - xuy * yux;

    if (qy == 0 && t == 0) {
        float* bb = out + BB_BASE + (size_t)rn * 12;
        bb[0] = n0;  bb[1] = n1;  bb[2] = n2;
        bb[3] = a0;  bb[4] = a1;  bb[5] = a2;
        bb[6] = c0;  bb[7] = c1;  bb[8] = c2;
        bb[9] = cb0; bb[10] = cb1; bb[11] = cb2;
        float* fr = out + FR_BASE + (size_t)rn * 9;
        fr[0] = xux; fr[1] = xuy; fr[2] = xuz;
        fr[3] = yux; fr[4] = yuy; fr[5] = yuz;
        fr[6] = zux; fr[7] = zuy; fr[8] = zuz;
    }

    __syncthreads();

    // ---- per-thread column base, shifted to this x-half's first x ----
    const int   yidx = qy * 4 + (col >> 4);
    const float gy = (float)yidx - 4.0f;          // VY/4
    const float gz = (float)(col & 15) - 8.0f;    // VZ/2
    // global x = xh*8 + k (k=0..7); gx = x - 8 = gx0 + k with gx0 = xh*8 - 8
    const float gx0 = (float)(xh * 8 - 8);
    float px = cb0 + gy * yux + gz * zux + gx0 * xux;
    float py = cb1 + gy * yuy + gz * zuy + gx0 * xuy;
    float pz = cb2 + gy * yuz + gz * zuz + gx0 * xuz;

    float Fx[8], Fy[8], Fz[8];
    #pragma unroll
    for (int k = 0; k < 8; ++k) { Fx[k] = 0.f; Fy[k] = 0.f; Fz[k] = 0.f; }

    // hot loop: 14 atoms x 8 x-values, fully unrolled; k is a compile-time
    // integer so d = k*xu + q takes the FFMA-imm form.
    // Weight: w = w0 * ry * sat(ry^2), ry = rsqrt(r2 + 1e-30) (R5/R9 math).
    #pragma unroll
    for (int a = 0; a < NA; ++a) {
        float4 at = s_atom[a];
        float qx = px - at.x, qy2_ = py - at.y, qz = pz - at.z;
        float w0 = at.w;
        #pragma unroll
        for (int k = 0; k < 8; ++k) {
            float fk = (float)k;
            float dx = fmaf(fk, xux, qx);
            float dy = fmaf(fk, xuy, qy2_);
            float dz = fmaf(fk, xuz, qz);
            float r2 = fmaf(dx, dx, fmaf(dy, dy, fmaf(dz, dz, 1e-30f)));
            float ry = rsqrtf(r2);
            float w  = w0 * (ry * __saturatef(ry * ry));
            Fx[k] = fmaf(w, dx, Fx[k]);
            Fy[k] = fmaf(w, dy, Fy[k]);
            Fz[k] = fmaf(w, dz, Fz[k]);
        }
    }

    // ---- normalize field vectors ----
    #pragma unroll
    for (int k = 0; k < 8; ++k) {
        float s = fmaf(Fx[k], Fx[k], fmaf(Fy[k], Fy[k], Fz[k] * Fz[k]));
        float sc = (s > 0.0f) ? rsqrtf(s) : 1.0f;
        Fx[k] *= sc; Fy[k] *= sc; Fz[k] *= sc;
    }

    // ---- exchange stencil boundary through SMEM ----
    // xh0's last value is global x=7 (local 7); xh1's first is x=8 (local 0).
    sEdge[xh][0][col] = xh ? Fx[0] : Fx[7];
    sEdge[xh][1][col] = xh ? Fy[0] : Fy[7];
    sEdge[xh][2][col] = xh ? Fz[0] : Fz[7];
    __syncthreads();
    // partner values: xh0 needs F[8] (stored by xh1), xh1 needs F[7] (by xh0)
    float pFx = sEdge[1 - xh][0][col];
    float pFy = sEdge[1 - xh][1][col];
    float pFz = sEdge[1 - xh][2][col];

    // ---- divergence along VX (axis 2); x: flip_last=False, y/z: True ----
    // out index = rn*4096 + x*256 + (yidx*16 + v);  yidx*16+v = qy*64 + col
    float* dv = out + DIV_BASE + (size_t)rn * VOXELS + (qy * 64 + col);
    if (xh == 0) {
        // global x = k (0..7)
        dv[0] = (Fx[1] - Fx[0]) + (Fy[1] - Fy[0]) + (Fz[1] - Fz[0]);
        #pragma unroll
        for (int i = 1; i <= 6; ++i) {
            float d = 0.5f * (Fx[i + 1] - Fx[i - 1])
                    + 0.5f * (Fy[i + 1] - Fy[i - 1])
                    + 0.5f * (Fz[i + 1] - Fz[i - 1]);
            dv[i * 256] = d;
        }
        // x=7: needs F[8] from partner
        dv[7 * 256] = 0.5f * (pFx - Fx[6])
                    + 0.5f * (pFy - Fy[6])
                    + 0.5f * (pFz - Fz[6]);
    } else {
        // global x = 8 + k (k=0..7)
        // x=8: needs F[7] from partner
        dv[8 * 256] = 0.5f * (Fx[1] - pFx)
                    + 0.5f * (Fy[1] - pFy)
                    + 0.5f * (Fz[1] - pFz);
        #pragma unroll
        for (int k = 1; k <= 6; ++k) {
            float d = 0.5f * (Fx[k + 1] - Fx[k - 1])
                    + 0.5f * (Fy[k + 1] - Fy[k - 1])
                    + 0.5f * (Fz[k + 1] - Fz[k - 1]);
            dv[(8 + k) * 256] = d;
        }
        // x=15: x-comp forward, y/z flipped (reference semantics)
        dv[15 * 256] = (Fx[7] - Fx[6]) + (Fy[6] - Fy[7]) + (Fz[6] - Fz[7]);
    }
}

extern "C" void kernel_launch(void* const* d_in, const int* in_sizes, int n_in,
                              void* d_out, int out_size)
{
    const float* C     = (const float*)d_in[0];
    const int*   Lw    = (const int*)  d_in[1];   // int32 view; width auto-detected
    const float* amask = (const float*)d_in[2];
    // d_in[3] = valid_mask: unused by the reference
    const float* amber = (const float*)d_in[4];

    pp_kernel<<<ZN * 4, 128>>>(C, Lw, amask, amber, (float*)d_out);
}

// round 15
// speedup vs baseline: 1.1133x; 1.0104x over previous
#include <cuda_runtime.h>
#include <cuda_bf16.h>

// Problem constants (fixed by reference: Z=2, N=256, A=14, AA=21, voxel 16^3, RES=1)
namespace {
constexpr int NA   = 14;
constexpr int ZN   = 2 * 256;               // 512 residues
constexpr int VOX  = 16;
constexpr int VOXELS = VOX * VOX * VOX;     // 4096
constexpr size_t BB_BASE  = 0;                                   // (ZN,4,3)
constexpr size_t DIV_BASE = (size_t)ZN * 12;                     // (ZN,1,16,16,16)
constexpr size_t FR_BASE  = DIV_BASE + (size_t)ZN * VOXELS;      // (ZN,3,3)

// local-k pair constants (k, k+1) as u64 fp32 bit patterns (lo=k, hi=k+1).
// Compile-time immediates -> no standing register cost.
__device__ constexpr unsigned long long GXK[4] = {
    0x3F80000000000000ULL,  // (0, 1)
    0x4040000040000000ULL,  // (2, 3)
    0x40A0000040800000ULL,  // (4, 5)
    0x40E0000040C00000ULL,  // (6, 7)
};
constexpr unsigned long long EPS2C = 0x0DA24260'0DA24260ULL;  // (1e-30f, 1e-30f)
}

// ---- packed dual-fp32 helpers (SASS FFMA2/FMUL2; two independent IEEE fp32 ops) ----
typedef unsigned long long u64;
__device__ __forceinline__ u64 pk2(float lo, float hi) {
    u64 d; asm("mov.b64 %0, {%1, %2};" : "=l"(d) : "f"(lo), "f"(hi)); return d;
}
__device__ __forceinline__ void upk2(u64 d, float& lo, float& hi) {
    asm("mov.b64 {%0, %1}, %2;" : "=f"(lo), "=f"(hi) : "l"(d));
}
__device__ __forceinline__ u64 fma2(u64 a, u64 b, u64 c) {
    u64 d; asm("fma.rn.f32x2 %0, %1, %2, %3;" : "=l"(d) : "l"(a), "l"(b), "l"(c)); return d;
}
__device__ __forceinline__ u64 mul2(u64 a, u64 b) {
    u64 d; asm("mul.rn.f32x2 %0, %1, %2;" : "=l"(d) : "l"(a), "l"(b)); return d;
}

// 4 CTAs per residue; CTA = 64 (y,v) columns x 2 x-halves = 128 threads.
// Each thread integrates 8 x-values as 4 packed pairs (24 accumulator regs,
// NO halo -- stencil boundary exchanged through SMEM). (128,9): 56-reg cap,
// 9 CTAs/SM = 36 warps/SM -- the config R12/R13 proved lifts issue to ~80%.
__global__ __launch_bounds__(128, 9)
void pp_kernel(const float* __restrict__ C,
               const int*   __restrict__ Lw,     // int32 view of L (int32 OR int64 storage)
               const float* __restrict__ amask,
               const float* __restrict__ amber,
               float* __restrict__ out)
{
    const int rn  = blockIdx.x >> 2;    // residue
    const int qy  = blockIdx.x & 3;     // which 4 y-planes
    const int t   = threadIdx.x;
    const int xh  = t >> 6;             // x-half: 0 -> x 0..7, 1 -> x 8..15
    const int col = t & 63;             // y_lo = col>>4, v = col&15

    __shared__ float4 s_atom[NA];           // x,y,z,charge
    __shared__ float  sEdge[2][3][64];      // [xh][comp][col]: normalized F at x=7 / x=8

    const float* Cr = C + (size_t)rn * NA * 3;

    // ---- atom + charge load (threads 0..13) ----
    if (t < NA) {
        // Detect int64-vs-int32 storage of L (values in [-1,20]): for int64 (LE)
        // every odd 32-bit word is 0 or -1; misdetect prob for int32 ~21^-16.
        int bad = 0;
        #pragma unroll
        for (int k = 0; k < 16; ++k) {
            int hv = __ldg(Lw + 2 * k + 1);
            bad |= (hv != 0) & (hv != -1);
        }
        int lv = bad ? __ldg(Lw + rn) : __ldg(Lw + 2 * rn);
        int lc = (lv == -1) ? 20 : lv;       // X_LBL = 20
        float q = __ldg(amber + lc * NA + t) * __ldg(amask + (size_t)rn * NA + t);
        s_atom[t] = make_float4(__ldg(Cr + 3 * t),
                                __ldg(Cr + 3 * t + 1),
                                __ldg(Cr + 3 * t + 2), q);
    }

    // ---- frame build (redundant per thread; broadcast loads; block-uniform) ----
    float n0 = __ldg(Cr + 0), n1 = __ldg(Cr + 1), n2 = __ldg(Cr + 2);
    float a0 = __ldg(Cr + 3), a1 = __ldg(Cr + 4), a2 = __ldg(Cr + 5);
    float c0 = __ldg(Cr + 6), c1 = __ldg(Cr + 7), c2 = __ldg(Cr + 8);

    float b1x = a0 - n0, b1y = a1 - n1, b1z = a2 - n2;
    float b2x = c0 - a0, b2y = c1 - a1, b2z = c2 - a2;
    float b3x = b1y * b2z - b1z * b2y;
    float b3y = b1z * b2x - b1x * b2z;
    float b3z = b1x * b2y - b1y * b2x;
    float cb0 = a0 - 0.58273431f * b2x + 0.56802827f * b1x - 0.54067466f * b3x;
    float cb1 = a1 - 0.58273431f * b2y + 0.56802827f * b1y - 0.54067466f * b3y;
    float cb2 = a2 - 0.58273431f * b2z + 0.56802827f * b1z - 0.54067466f * b3z;

    float yx = cb0 - a0, yy = cb1 - a1, yz = cb2 - a2;
    float yn = sqrtf(yx * yx + yy * yy + yz * yz);
    float yi = 1.0f / fmaxf(yn, 1e-6f);
    float yux = yx * yi, yuy = yy * yi, yuz = yz * yi;

    // scalar projection subtracted from every component (replicates reference)
    float xrx = c0 - n0, xry = c1 - n1, xrz = c2 - n2;
    float xp = xrx * yux + xry * yuy + xrz * yuz;
    float xx = xrx - xp, xy = xry - xp, xz = xrz - xp;
    float xn = sqrtf(xx * xx + xy * xy + xz * xz);
    float xi = 1.0f / fmaxf(xn, 1e-6f);
    float xux = xx * xi, xuy = xy * xi, xuz = xz * xi;

    float zux = xuy * yuz - xuz * yuy;
    float zuy = xuz * yux - xux * yuz;
    float zuz = xux * yuy - xuy * yux;

    if (qy == 0 && t == 0) {
        float* bb = out + BB_BASE + (size_t)rn * 12;
        bb[0] = n0;  bb[1] = n1;  bb[2] = n2;
        bb[3] = a0;  bb[4] = a1;  bb[5] = a2;
        bb[6] = c0;  bb[7] = c1;  bb[8] = c2;
        bb[9] = cb0; bb[10] = cb1; bb[11] = cb2;
        float* fr = out + FR_BASE + (size_t)rn * 9;
        fr[0] = xux; fr[1] = xuy; fr[2] = xuz;
        fr[3] = yux; fr[4] = yuy; fr[5] = yuz;
        fr[6] = zux; fr[7] = zuy; fr[8] = zuz;
    }

    __syncthreads();

    // ---- per-thread column base, shifted to this x-half's first x ----
    const int   yidx = qy * 4 + (col >> 4);
    const float gy = (float)yidx - 4.0f;          // VY/4
    const float gz = (float)(col & 15) - 8.0f;    // VZ/2
    // global x = xh*8 + k (k=0..7); gx = x - 8 = gx0 + k, gx0 = xh*8 - 8
    const float gx0 = (float)(xh * 8 - 8);
    float px = cb0 + gy * yux + gz * zux + gx0 * xux;
    float py = cb1 + gy * yuy + gz * zuy + gx0 * xuy;
    float pz = cb2 + gy * yuz + gz * zuz + gx0 * xuz;

    // packed broadcast of the x-axis (block-uniform)
    const u64 xux2 = pk2(xux, xux), xuy2 = pk2(xuy, xuy), xuz2 = pk2(xuz, xuz);

    u64 Fx2[4], Fy2[4], Fz2[4];
    #pragma unroll
    for (int j = 0; j < 4; ++j) { Fx2[j] = 0ull; Fy2[j] = 0ull; Fz2[j] = 0ull; }

    // hot loop: 14 atoms x 4 packed k-pairs, fully unrolled.
    // Weight: w = w0 * ry * sat(ry^2), ry = rsqrt(r2 + 1e-30)  (R5/R9 math)
    #pragma unroll
    for (int a = 0; a < NA; ++a) {
        float4 at = s_atom[a];
        float qx = px - at.x, qyv = py - at.y, qz = pz - at.z;
        const u64 qx2 = pk2(qx, qx), qy2 = pk2(qyv, qyv), qz2 = pk2(qz, qz);
        const float w0 = at.w;
        #pragma unroll
        for (int j = 0; j < 4; ++j) {
            u64 dx2 = fma2(GXK[j], xux2, qx2);
            u64 dy2 = fma2(GXK[j], xuy2, qy2);
            u64 dz2 = fma2(GXK[j], xuz2, qz2);
            u64 r22 = fma2(dx2, dx2, fma2(dy2, dy2, fma2(dz2, dz2, EPS2C)));
            float ra, rb; upk2(r22, ra, rb);
            float rya = rsqrtf(ra), ryb = rsqrtf(rb);
            float wa = w0 * (rya * __saturatef(rya * rya));
            float wb = w0 * (ryb * __saturatef(ryb * ryb));
            u64 wp = pk2(wa, wb);
            Fx2[j] = fma2(wp, dx2, Fx2[j]);
            Fy2[j] = fma2(wp, dy2, Fy2[j]);
            Fz2[j] = fma2(wp, dz2, Fz2[j]);
        }
    }

    // ---- normalize field vectors (packed) ----
    #pragma unroll
    for (int j = 0; j < 4; ++j) {
        u64 s2 = fma2(Fx2[j], Fx2[j], fma2(Fy2[j], Fy2[j], mul2(Fz2[j], Fz2[j])));
        float sa, sb; upk2(s2, sa, sb);
        float sca = (sa > 0.0f) ? rsqrtf(sa) : 1.0f;
        float scb = (sb > 0.0f) ? rsqrtf(sb) : 1.0f;
        u64 sc2 = pk2(sca, scb);
        Fx2[j] = mul2(Fx2[j], sc2);
        Fy2[j] = mul2(Fy2[j], sc2);
        Fz2[j] = mul2(Fz2[j], sc2);
    }

    // unpack for the finite difference
    float Fx[8], Fy[8], Fz[8];
    #pragma unroll
    for (int j = 0; j < 4; ++j) {
        upk2(Fx2[j], Fx[2 * j], Fx[2 * j + 1]);
        upk2(Fy2[j], Fy[2 * j], Fy[2 * j + 1]);
        upk2(Fz2[j], Fz[2 * j], Fz[2 * j + 1]);
    }

    // ---- exchange stencil boundary through SMEM ----
    sEdge[xh][0][col] = xh ? Fx[0] : Fx[7];
    sEdge[xh][1][col] = xh ? Fy[0] : Fy[7];
    sEdge[xh][2][col] = xh ? Fz[0] : Fz[7];
    __syncthreads();
    float pFx = sEdge[1 - xh][0][col];
    float pFy = sEdge[1 - xh][1][col];
    float pFz = sEdge[1 - xh][2][col];

    // ---- divergence along VX (axis 2); x: flip_last=False, y/z: True ----
    // out index = rn*4096 + x*256 + (yidx*16 + v);  yidx*16+v = qy*64 + col
    float* dv = out + DIV_BASE + (size_t)rn * VOXELS + (qy * 64 + col);
    if (xh == 0) {
        dv[0] = (Fx[1] - Fx[0]) + (Fy[1] - Fy[0]) + (Fz[1] - Fz[0]);
        #pragma unroll
        for (int i = 1; i <= 6; ++i) {
            float d = 0.5f * (Fx[i + 1] - Fx[i - 1])
                    + 0.5f * (Fy[i + 1] - Fy[i - 1])
                    + 0.5f * (Fz[i + 1] - Fz[i - 1]);
            dv[i * 256] = d;
        }
        dv[7 * 256] = 0.5f * (pFx - Fx[6])
                    + 0.5f * (pFy - Fy[6])
                    + 0.5f * (pFz - Fz[6]);
    } else {
        dv[8 * 256] = 0.5f * (Fx[1] - pFx)
                    + 0.5f * (Fy[1] - pFy)
                    + 0.5f * (Fz[1] - pFz);
        #pragma unroll
        for (int k = 1; k <= 6; ++k) {
            float d = 0.5f * (Fx[k + 1] - Fx[k - 1])
                    + 0.5f * (Fy[k + 1] - Fy[k - 1])
                    + 0.5f * (Fz[k + 1] - Fz[k - 1]);
            dv[(8 + k) * 256] = d;
        }
        dv[15 * 256] = (Fx[7] - Fx[6]) + (Fy[6] - Fy[7]) + (Fz[6] - Fz[7]);
    }
}

extern "C" void kernel_launch(void* const* d_in, const int* in_sizes, int n_in,
                              void* d_out, int out_size)
{
    const float* C     = (const float*)d_in[0];
    const int*   Lw    = (const int*)  d_in[1];   // int32 view; width auto-detected
    const float* amask = (const float*)d_in[2];
    // d_in[3] = valid_mask: unused by the reference
    const float* amber = (const float*)d_in[4];

    pp_kernel<<<ZN * 4, 128>>>(C, Lw, amask, amber, (float*)d_out);
}

// round 17
// speedup vs baseline: 1.1892x; 1.0682x over previous
#include <cuda_runtime.h>
#include <cuda_bf16.h>

// Problem constants (fixed by reference: Z=2, N=256, A=14, AA=21, voxel 16^3, RES=1)
namespace {
constexpr int NA   = 14;
constexpr int ZN   = 2 * 256;               // 512 residues
constexpr int VOX  = 16;
constexpr int VOXELS = VOX * VOX * VOX;     // 4096
constexpr size_t BB_BASE  = 0;                                   // (ZN,4,3)
constexpr size_t DIV_BASE = (size_t)ZN * 12;                     // (ZN,1,16,16,16)
constexpr size_t FR_BASE  = DIV_BASE + (size_t)ZN * VOXELS;      // (ZN,3,3)
}

// 4 CTAs per residue; CTA = 64 (y,v) columns x 2 x-halves = 128 threads.
// Each thread covers 8 x-values. FACTORIZED accumulation:
//   F(k) = P_k * Sw(k) - Sc(k),  Sw = sum_a w, Sc = sum_a w*c_a
// removes the per-interaction d-vector (13 -> 10 issues) and SHORTENS the
// r2 chain via r2 = (k+s)^2 + (q2 - s^2). Stencil boundary via SMEM.
// (128,9): 56-reg cap -> 9 CTAs/SM = 36 warps/SM (R13-proven ~80% issue).
__global__ __launch_bounds__(128, 9)
void pp_kernel(const float* __restrict__ C,
               const int*   __restrict__ Lw,     // int32 view of L (int32 OR int64 storage)
               const float* __restrict__ amask,
               const float* __restrict__ amber,
               float* __restrict__ out)
{
    const int rn  = blockIdx.x >> 2;    // residue
    const int qy  = blockIdx.x & 3;     // which 4 y-planes
    const int t   = threadIdx.x;
    const int xh  = t >> 6;             // x-half: 0 -> x 0..7, 1 -> x 8..15
    const int col = t & 63;             // y_lo = col>>4, v = col&15

    __shared__ float4 s_atom[NA];           // x,y,z,charge
    __shared__ float  sEdge[2][3][64];      // [xh][comp][col]: normalized F at x=7 / x=8

    const float* Cr = C + (size_t)rn * NA * 3;

    // ---- atom + charge load (threads 0..13) ----
    if (t < NA) {
        // Detect int64-vs-int32 storage of L (values in [-1,20]): for int64 (LE)
        // every odd 32-bit word is 0 or -1; misdetect prob for int32 ~21^-16.
        int bad = 0;
        #pragma unroll
        for (int k = 0; k < 16; ++k) {
            int hv = __ldg(Lw + 2 * k + 1);
            bad |= (hv != 0) & (hv != -1);
        }
        int lv = bad ? __ldg(Lw + rn) : __ldg(Lw + 2 * rn);
        int lc = (lv == -1) ? 20 : lv;       // X_LBL = 20
        float q = __ldg(amber + lc * NA + t) * __ldg(amask + (size_t)rn * NA + t);
        s_atom[t] = make_float4(__ldg(Cr + 3 * t),
                                __ldg(Cr + 3 * t + 1),
                                __ldg(Cr + 3 * t + 2), q);
    }

    // ---- frame build (redundant per thread; broadcast loads; block-uniform) ----
    float n0 = __ldg(Cr + 0), n1 = __ldg(Cr + 1), n2 = __ldg(Cr + 2);
    float a0 = __ldg(Cr + 3), a1 = __ldg(Cr + 4), a2 = __ldg(Cr + 5);
    float c0 = __ldg(Cr + 6), c1 = __ldg(Cr + 7), c2 = __ldg(Cr + 8);

    float b1x = a0 - n0, b1y = a1 - n1, b1z = a2 - n2;
    float b2x = c0 - a0, b2y = c1 - a1, b2z = c2 - a2;
    float b3x = b1y * b2z - b1z * b2y;
    float b3y = b1z * b2x - b1x * b2z;
    float b3z = b1x * b2y - b1y * b2x;
    float cb0 = a0 - 0.58273431f * b2x + 0.56802827f * b1x - 0.54067466f * b3x;
    float cb1 = a1 - 0.58273431f * b2y + 0.56802827f * b1y - 0.54067466f * b3y;
    float cb2 = a2 - 0.58273431f * b2z + 0.56802827f * b1z - 0.54067466f * b3z;

    float yx = cb0 - a0, yy = cb1 - a1, yz = cb2 - a2;
    float yn = sqrtf(yx * yx + yy * yy + yz * yz);
    float yi = 1.0f / fmaxf(yn, 1e-6f);
    float yux = yx * yi, yuy = yy * yi, yuz = yz * yi;

    // scalar projection subtracted from every component (replicates reference)
    float xrx = c0 - n0, xry = c1 - n1, xrz = c2 - n2;
    float xp = xrx * yux + xry * yuy + xrz * yuz;
    float xx = xrx - xp, xy = xry - xp, xz = xrz - xp;
    float xn = sqrtf(xx * xx + xy * xy + xz * xz);
    float xi = 1.0f / fmaxf(xn, 1e-6f);
    float xux = xx * xi, xuy = xy * xi, xuz = xz * xi;

    float zux = xuy * yuz - xuz * yuy;
    float zuy = xuz * yux - xux * yuz;
    float zuz = xux * yuy - xuy * yux;

    if (qy == 0 && t == 0) {
        float* bb = out + BB_BASE + (size_t)rn * 12;
        bb[0] = n0;  bb[1] = n1;  bb[2] = n2;
        bb[3] = a0;  bb[4] = a1;  bb[5] = a2;
        bb[6] = c0;  bb[7] = c1;  bb[8] = c2;
        bb[9] = cb0; bb[10] = cb1; bb[11] = cb2;
        float* fr = out + FR_BASE + (size_t)rn * 9;
        fr[0] = xux; fr[1] = xuy; fr[2] = xuz;
        fr[3] = yux; fr[4] = yuy; fr[5] = yuz;
        fr[6] = zux; fr[7] = zuy; fr[8] = zuz;
    }

    __syncthreads();

    // ---- per-thread column base, shifted to this x-half's first x ----
    const int   yidx = qy * 4 + (col >> 4);
    const float gy = (float)yidx - 4.0f;          // VY/4
    const float gz = (float)(col & 15) - 8.0f;    // VZ/2
    // global x = xh*8 + k (k=0..7); gx = gx0 + k, gx0 = xh*8 - 8
    const float gx0 = (float)(xh * 8 - 8);
    float px = cb0 + gy * yux + gz * zux + gx0 * xux;
    float py = cb1 + gy * yuy + gz * zuy + gx0 * xuy;
    float pz = cb2 + gy * yuz + gz * zuz + gx0 * xuz;

    // factorized accumulators: Sw(k), Sc(k) = sum_a w * c_a
    float Sw[8], Sx[8], Sy[8], Sz[8];
    #pragma unroll
    for (int k = 0; k < 8; ++k) { Sw[k] = 0.f; Sx[k] = 0.f; Sy[k] = 0.f; Sz[k] = 0.f; }

    // hot loop: 14 atoms x 8 x-values, fully unrolled.
    //   q = p - c_a;  s = xu.q;  h = max(q2 - s^2, 0) + 1e-30
    //   r2(k) = (k+s)^2 + h     (exact identity: |q + k*xu|^2, xu unit)
    //   w = w0 * ry * sat(ry^2), ry = rsqrt(r2)   (R5/R9/R13 weight math)
    #pragma unroll
    for (int a = 0; a < NA; ++a) {
        float4 at = s_atom[a];
        float qx = px - at.x, qyv = py - at.y, qz = pz - at.z;
        float s  = qx * xux + qyv * xuy + qz * xuz;
        float q2 = qx * qx + qyv * qyv + qz * qz;
        // clamp: q2 - s^2 >= 0 mathematically; rounding can go negative ->
        // rsqrt(neg)=NaN. eps keeps r2 > 0 at exact coincidence (w finite,
        // contribution P-c = 0 as in the reference).
        float h = fmaxf(fmaf(-s, s, q2), 0.0f) + 1e-30f;
        float w0 = at.w;
        float cax = at.x, cay = at.y, caz = at.z;
        #pragma unroll
        for (int k = 0; k < 8; ++k) {
            float e  = (float)k + s;
            float r2 = fmaf(e, e, h);
            float ry = rsqrtf(r2);
            float w  = w0 * (ry * __saturatef(ry * ry));
            Sw[k] += w;
            Sx[k] = fmaf(w, cax, Sx[k]);
            Sy[k] = fmaf(w, cay, Sy[k]);
            Sz[k] = fmaf(w, caz, Sz[k]);
        }
    }

    // ---- reconstruct fields, normalize ----
    float Fx[8], Fy[8], Fz[8];
    #pragma unroll
    for (int k = 0; k < 8; ++k) {
        float fk  = (float)k;
        float Pkx = fmaf(fk, xux, px);
        float Pky = fmaf(fk, xuy, py);
        float Pkz = fmaf(fk, xuz, pz);
        float fx = fmaf(Pkx, Sw[k], -Sx[k]);
        float fy = fmaf(Pky, Sw[k], -Sy[k]);
        float fz = fmaf(Pkz, Sw[k], -Sz[k]);
        float s  = fmaf(fx, fx, fmaf(fy, fy, fz * fz));
        float sc = (s > 0.0f) ? rsqrtf(s) : 1.0f;
        Fx[k] = fx * sc; Fy[k] = fy * sc; Fz[k] = fz * sc;
    }

    // ---- exchange stencil boundary through SMEM ----
    sEdge[xh][0][col] = xh ? Fx[0] : Fx[7];
    sEdge[xh][1][col] = xh ? Fy[0] : Fy[7];
    sEdge[xh][2][col] = xh ? Fz[0] : Fz[7];
    __syncthreads();
    float pFx = sEdge[1 - xh][0][col];
    float pFy = sEdge[1 - xh][1][col];
    float pFz = sEdge[1 - xh][2][col];

    // ---- divergence along VX (axis 2); x: flip_last=False, y/z: True ----
    // out index = rn*4096 + x*256 + (yidx*16 + v);  yidx*16+v = qy*64 + col
    float* dv = out + DIV_BASE + (size_t)rn * VOXELS + (qy * 64 + col);
    if (xh == 0) {
        dv[0] = (Fx[1] - Fx[0]) + (Fy[1] - Fy[0]) + (Fz[1] - Fz[0]);
        #pragma unroll
        for (int i = 1; i <= 6; ++i) {
            float d = 0.5f * (Fx[i + 1] - Fx[i - 1])
                    + 0.5f * (Fy[i + 1] - Fy[i - 1])
                    + 0.5f * (Fz[i + 1] - Fz[i - 1]);
            dv[i * 256] = d;
        }
        dv[7 * 256] = 0.5f * (pFx - Fx[6])
                    + 0.5f * (pFy - Fy[6])
                    + 0.5f * (pFz - Fz[6]);
    } else {
        dv[8 * 256] = 0.5f * (Fx[1] - pFx)
                    + 0.5f * (Fy[1] - pFy)
                    + 0.5f * (Fz[1] - pFz);
        #pragma unroll
        for (int k = 1; k <= 6; ++k) {
            float d = 0.5f * (Fx[k + 1] - Fx[k - 1])
                    + 0.5f * (Fy[k + 1] - Fy[k - 1])
                    + 0.5f * (Fz[k + 1] - Fz[k - 1]);
            dv[(8 + k) * 256] = d;
        }
        dv[15 * 256] = (Fx[7] - Fx[6]) + (Fy[6] - Fy[7]) + (Fz[6] - Fz[7]);
    }
}

extern "C" void kernel_launch(void* const* d_in, const int* in_sizes, int n_in,
                              void* d_out, int out_size)
{
    const float* C     = (const float*)d_in[0];
    const int*   Lw    = (const int*)  d_in[1];   // int32 view; width auto-detected
    const float* amask = (const float*)d_in[2];
    // d_in[3] = valid_mask: unused by the reference
    const float* amber = (const float*)d_in[4];

    pp_kernel<<<ZN * 4, 128>>>(C, Lw, amask, amber, (float*)d_out);
}